// round 15
// baseline (speedup 1.0000x reference)
#include <cuda_runtime.h>
#include <cuda_bf16.h>
#include <cstdint>

// Problem constants
#define MCC    10
#define INC    16
#define OUTC   32
#define HW_IN  128
#define HW_OUT 64
#define KTOT   144          // 3*3*16
#define NTOT   320
#define NPX    32768        // total output pixels (8 * 64 * 64)

// Tiles: CTA walks contiguous (pixel-tile, slab) units; 192 thr, 6 warps of 32x32
#define THREADS 192
#define CH_CTA  64
#define PX_CTA  96
#define AKB     304         // K row stride in bytes (152 bf16 = 19*16B, conflict-free)
#define PXTILES 342         // ceil(32768 / 96)
#define NSLABS  5
#define UNITS   (PXTILES * NSLABS)   // 1710
#define GRID    296                  // 148 SMs x 2 CTAs -> exactly 1 wave
#define UBASE   (UNITS / GRID)       // 5
#define UEXTRA  (UNITS - GRID * UBASE) // 230

#define X_BYTES (PX_CTA * AKB)          // 29184
#define W_BYTES (CH_CTA * AKB)          // 19456
#define OFF_XHI 0
#define OFF_XLO (X_BYTES)
#define OFF_WHI (2 * X_BYTES)
#define OFF_WLO (2 * X_BYTES + W_BYTES)
#define SMEM_BYTES (2 * X_BYTES + 2 * W_BYTES)   // 97280 -> 2 CTAs/SM

// Pre-split weights, [n][k] layout (n = mc*32+oc), k padded to 152
#define WKP 152
__device__ __nv_bfloat16 d_Wh[NTOT * WKP];
__device__ __nv_bfloat16 d_Wl[NTOT * WKP];

__device__ __forceinline__ uint32_t smem_u32(const void* p) {
    uint32_t a;
    asm("{ .reg .u64 t; cvta.to.shared.u64 t, %1; cvt.u32.u64 %0, t; }" : "=r"(a) : "l"(p));
    return a;
}
__device__ __forceinline__ void ldmx4(uint32_t addr, uint32_t &r0, uint32_t &r1,
                                      uint32_t &r2, uint32_t &r3) {
    asm volatile("ldmatrix.sync.aligned.m8n8.x4.shared.b16 {%0,%1,%2,%3}, [%4];"
                 : "=r"(r0), "=r"(r1), "=r"(r2), "=r"(r3) : "r"(addr));
}
__device__ __forceinline__ void mma16816(float* d, const uint32_t* a, const uint32_t* bb) {
    asm volatile(
        "mma.sync.aligned.m16n8k16.row.col.f32.bf16.bf16.f32 "
        "{%0,%1,%2,%3}, {%4,%5,%6,%7}, {%8,%9}, {%0,%1,%2,%3};"
        : "+f"(d[0]), "+f"(d[1]), "+f"(d[2]), "+f"(d[3])
        : "r"(a[0]), "r"(a[1]), "r"(a[2]), "r"(a[3]), "r"(bb[0]), "r"(bb[1]));
}
__device__ __forceinline__ void cp16(uint32_t saddr, const void* gptr) {
    asm volatile("cp.async.cg.shared.global [%0], [%1], 16;"
                 :: "r"(saddr), "l"(gptr) : "memory");
}
__device__ __forceinline__ void cp_commit() {
    asm volatile("cp.async.commit_group;" ::: "memory");
}
__device__ __forceinline__ void cp_wait0() {
    asm volatile("cp.async.wait_group 0;" ::: "memory");
}
__device__ __forceinline__ void fast_sincos(float v, float &s, float &c) {
    float t = rintf(v * 0.15915494309189535f);
    float r = fmaf(t, -6.2831855f, v);
    r = fmaf(t, 1.7484555e-7f, r);
    s = __sinf(r);
    c = __cosf(r);
}
__device__ __forceinline__ uint16_t bfbits(__nv_bfloat16 h) {
    uint16_t u; *(__nv_bfloat16*)&u = h; return u;
}

// ---------- weight materialization: DESTINATION-indexed (race-free) ----------
__global__ void prep_w_kernel(const float* __restrict__ mean,
                              const float* __restrict__ ls,
                              const float* __restrict__ eps) {
    int i = blockIdx.x * 256 + threadIdx.x;     // destination slot in [NTOT*WKP)
    if (i >= NTOT * WKP) return;
    int n  = i / WKP;          // n = mc*32 + oc
    int kk = i - n * WKP;      // 0..151
    float w = 0.f;
    if (kk < KTOT) {
        int mc = n >> 5;
        int oc = n & 31;
        float e = eps[(mc * KTOT + kk) * OUTC + oc];
        w = fmaf(e, expf(0.5f * ls[kk * OUTC + oc]), mean[kk * OUTC + oc]);
    }
    __nv_bfloat16 hi = __float2bfloat16_rn(w);
    __nv_bfloat16 lo = __float2bfloat16_rn(w - __bfloat162float(hi));
    d_Wh[i] = hi;
    d_Wl[i] = lo;
}

__global__ void __launch_bounds__(THREADS, 2)
conv_rff_hmma_kernel(const float* __restrict__ x,
                     const float* __restrict__ theta,
                     float* __restrict__ out) {
    extern __shared__ char sm[];
    const uint32_t smb = smem_u32(sm);

    const int tid  = threadIdx.x;
    const int wid  = tid >> 5;
    const int lane = tid & 31;

    // Contiguous unit range for this CTA; odd CTAs walk it in reverse
    const int g   = blockIdx.x;
    const int cnt = UBASE + (g < UEXTRA ? 1 : 0);
    const int u0  = g * UBASE + (g < UEXTRA ? g : UEXTRA);
    const bool rev = (g & 1);

    // Warp tiling constants
    const int chbase = (wid & 1) * 32;    // 0 or 32
    const int pxw    = (wid >> 1) * 32;   // 0, 32, 64
    const uint32_t a_off = (uint32_t)((lane & 15) * AKB + (lane >> 4) * 16);
    const uint32_t b_off = (uint32_t)(((lane >> 4) * 8 + (lane & 7)) * AKB +
                                      ((lane >> 3) & 1) * 16);
    const uint32_t wbase_hi = smb + OFF_WHI + chbase * AKB + a_off;
    const uint32_t wbase_lo = smb + OFF_WLO + chbase * AKB + a_off;
    const uint32_t xbase_hi = smb + OFF_XHI + pxw * AKB + b_off;
    const uint32_t xbase_lo = smb + OFF_XLO + pxw * AKB + b_off;
    const float scale = expf(0.5f * theta[0]) * 0.0027621358640644f; // 1/sqrt(32*64*64)
    const int l2 = lane >> 2;
    const int l3 = lane & 3;

    auto unit_at = [&](int ui) { return rev ? (u0 + cnt - 1 - ui) : (u0 + ui); };

    auto stage_X = [&](int tile) {
        const int px0 = tile * PX_CTA;
        char* Xh = sm + OFF_XHI;
        char* Xl = sm + OFF_XLO;
        #pragma unroll 3
        for (int i = tid; i < PX_CTA * (KTOT / 4); i += THREADS) {   // 18 iters
            int q  = i / PX_CTA;        // k-quad 0..35
            int px = i - q * PX_CTA;
            int k0 = q * 4;
            int kh  = k0 / 48;
            int rem = k0 - kh * 48;
            int kw  = rem >> 4;
            int c0  = rem & 15;         // quads never straddle (kh,kw)
            int gp  = px0 + px;
            int b   = gp >> 12;
            int oy  = (gp >> 6) & 63;
            int ox  = gp & 63;
            int iy  = 2 * oy + kh - 1;
            int ix  = 2 * ox + kw - 1;
            bool valid = (gp < NPX) && ((unsigned)iy < (unsigned)HW_IN)
                                     && ((unsigned)ix < (unsigned)HW_IN);
            const float* xp = x + (((size_t)b * INC + c0) * HW_IN + iy) * HW_IN + ix;
            float v[4];
            #pragma unroll
            for (int j = 0; j < 4; ++j)
                v[j] = valid ? xp[(size_t)j * HW_IN * HW_IN] : 0.f;
            uint16_t hu[4], lu[4];
            #pragma unroll
            for (int j = 0; j < 4; ++j) {
                __nv_bfloat16 h = __float2bfloat16_rn(v[j]);
                __nv_bfloat16 l = __float2bfloat16_rn(v[j] - __bfloat162float(h));
                hu[j] = bfbits(h); lu[j] = bfbits(l);
            }
            uint32_t off = (uint32_t)(px * AKB + k0 * 2);
            *(uint2*)(Xh + off) = make_uint2((uint32_t)hu[0] | ((uint32_t)hu[1] << 16),
                                             (uint32_t)hu[2] | ((uint32_t)hu[3] << 16));
            *(uint2*)(Xl + off) = make_uint2((uint32_t)lu[0] | ((uint32_t)lu[1] << 16),
                                             (uint32_t)lu[2] | ((uint32_t)lu[3] << 16));
        }
    };

    auto prefetch_W = [&](int slab) {
        const char* gh = (const char*)(d_Wh + (size_t)slab * CH_CTA * WKP);
        const char* gl = (const char*)(d_Wl + (size_t)slab * CH_CTA * WKP);
        #pragma unroll 2
        for (int i = tid; i < W_BYTES / 16; i += THREADS) {   // 1216 chunks
            cp16(smb + OFF_WHI + i * 16, gh + i * 16);
            cp16(smb + OFF_WLO + i * 16, gl + i * 16);
        }
        cp_commit();
    };

    // ---- prologue: stage first X + prefetch first W ----
    {
        int u = unit_at(0);
        prefetch_W(u % NSLABS);
        stage_X(u / NSLABS);
    }

    int cur_tile = unit_at(0) / NSLABS;

    for (int ui = 0; ui < cnt; ++ui) {
        const int u    = unit_at(ui);
        const int tile = u / NSLABS;
        const int slab = u - tile * NSLABS;
        const int px0  = tile * PX_CTA;

        cp_wait0();
        __syncthreads();   // X + W visible to all warps

        float acc[2][4][4];
        #pragma unroll
        for (int mi = 0; mi < 2; ++mi)
            #pragma unroll
            for (int ni = 0; ni < 4; ++ni)
                #pragma unroll
                for (int c = 0; c < 4; ++c)
                    acc[mi][ni][c] = 0.f;

        // ---- k-chunk-major mainloop, fragment double-buffered ----
        uint32_t fbh[2][4][2], fbl[2][4][2];   // X fragments hi/lo
        uint32_t fah[2][2][4], fal[2][2][4];   // W fragments hi/lo

        #define LOAD_FRAGS(KC, BUF) do {                                          \
            const uint32_t kb_ = (uint32_t)(KC) * 32;                             \
            uint32_t r0_, r1_, r2_, r3_;                                          \
            ldmx4(xbase_hi + kb_, r0_, r1_, r2_, r3_);                            \
            fbh[BUF][0][0]=r0_; fbh[BUF][0][1]=r1_;                               \
            fbh[BUF][1][0]=r2_; fbh[BUF][1][1]=r3_;                               \
            ldmx4(xbase_hi + 16*AKB + kb_, r0_, r1_, r2_, r3_);                   \
            fbh[BUF][2][0]=r0_; fbh[BUF][2][1]=r1_;                               \
            fbh[BUF][3][0]=r2_; fbh[BUF][3][1]=r3_;                               \
            ldmx4(xbase_lo + kb_, r0_, r1_, r2_, r3_);                            \
            fbl[BUF][0][0]=r0_; fbl[BUF][0][1]=r1_;                               \
            fbl[BUF][1][0]=r2_; fbl[BUF][1][1]=r3_;                               \
            ldmx4(xbase_lo + 16*AKB + kb_, r0_, r1_, r2_, r3_);                   \
            fbl[BUF][2][0]=r0_; fbl[BUF][2][1]=r1_;                               \
            fbl[BUF][3][0]=r2_; fbl[BUF][3][1]=r3_;                               \
            ldmx4(wbase_hi + kb_, fah[BUF][0][0], fah[BUF][0][1],                 \
                                   fah[BUF][0][2], fah[BUF][0][3]);               \
            ldmx4(wbase_hi + 16*AKB + kb_, fah[BUF][1][0], fah[BUF][1][1],        \
                                   fah[BUF][1][2], fah[BUF][1][3]);               \
            ldmx4(wbase_lo + kb_, fal[BUF][0][0], fal[BUF][0][1],                 \
                                   fal[BUF][0][2], fal[BUF][0][3]);               \
            ldmx4(wbase_lo + 16*AKB + kb_, fal[BUF][1][0], fal[BUF][1][1],        \
                                   fal[BUF][1][2], fal[BUF][1][3]);               \
        } while (0)

        LOAD_FRAGS(0, 0);
        #pragma unroll
        for (int kc = 0; kc < 9; ++kc) {
            const int cur = kc & 1;
            if (kc < 8) LOAD_FRAGS(kc + 1, cur ^ 1);
            // s0 + s1: W_hi x (X_hi, X_lo)
            #pragma unroll
            for (int ni = 0; ni < 4; ++ni) {
                mma16816(acc[0][ni], fah[cur][0], fbh[cur][ni]);
                mma16816(acc[1][ni], fah[cur][1], fbh[cur][ni]);
            }
            #pragma unroll
            for (int ni = 0; ni < 4; ++ni) {
                mma16816(acc[0][ni], fah[cur][0], fbl[cur][ni]);
                mma16816(acc[1][ni], fah[cur][1], fbl[cur][ni]);
            }
            // s2: W_lo x X_hi
            #pragma unroll
            for (int ni = 0; ni < 4; ++ni) {
                mma16816(acc[0][ni], fal[cur][0], fbh[cur][ni]);
                mma16816(acc[1][ni], fal[cur][1], fbh[cur][ni]);
            }
        }
        #undef LOAD_FRAGS

        __syncthreads();   // all warps done reading X/W; buffers may be refilled

        // ---- prefetch next unit's W under the epilogue ----
        int next_tile = -1;
        if (ui + 1 < cnt) {
            int un = unit_at(ui + 1);
            prefetch_W(un % NSLABS);
            next_tile = un / NSLABS;
        }

        // ---- Epilogue for this unit (overlaps W prefetch latency) ----
        #pragma unroll
        for (int mi = 0; mi < 2; ++mi) {
            #pragma unroll
            for (int msub = 0; msub < 2; ++msub) {
                int ch  = chbase + mi * 16 + msub * 8 + l2;
                int ngl = slab * CH_CTA + ch;                // global channel [0,320)
                int chan = (ngl >> 5) * 64 + (ngl & 31);     // mc*64 + oc
                #pragma unroll
                for (int ni = 0; ni < 4; ++ni) {
                    int gp = px0 + pxw + ni * 8 + 2 * l3;
                    if (gp >= NPX) continue;
                    int b  = gp >> 12;
                    int oy = (gp >> 6) & 63;
                    int ox = gp & 63;
                    float* basec = out + ((size_t)(b * (MCC * 2 * OUTC) + chan)) * (HW_OUT * HW_OUT)
                                       + oy * HW_OUT + ox;
                    float* bases = basec + (size_t)OUTC * HW_OUT * HW_OUT;
                    float v0 = acc[mi][ni][msub * 2 + 0];
                    float v1 = acc[mi][ni][msub * 2 + 1];
                    float s0, c0, s1, c1;
                    fast_sincos(v0, s0, c0);
                    fast_sincos(v1, s1, c1);
                    *(float2*)basec = make_float2(scale * c0, scale * c1);
                    *(float2*)bases = make_float2(scale * s0, scale * s1);
                }
            }
        }

        // ---- restage X if the next unit is a new pixel tile ----
        if (next_tile >= 0 && next_tile != cur_tile) {
            stage_X(next_tile);
            cur_tile = next_tile;
        }
    }
}

extern "C" void kernel_launch(void* const* d_in, const int* in_sizes, int n_in,
                              void* d_out, int out_size) {
    const float* x     = (const float*)d_in[0];
    const float* theta = (const float*)d_in[1];
    const float* mean  = (const float*)d_in[2];
    const float* ls    = (const float*)d_in[3];
    const float* eps   = (const float*)d_in[4];
    float* out = (float*)d_out;

    prep_w_kernel<<<(NTOT * WKP + 255) / 256, 256>>>(mean, ls, eps);

    cudaFuncSetAttribute(conv_rff_hmma_kernel,
                         cudaFuncAttributeMaxDynamicSharedMemorySize, SMEM_BYTES);
    conv_rff_hmma_kernel<<<GRID, THREADS, SMEM_BYTES>>>(x, theta, out);
}

// round 17
// speedup vs baseline: 1.2893x; 1.2893x over previous
#include <cuda_runtime.h>
#include <cuda_fp16.h>
#include <cstdint>

// Problem constants
#define MCC    10
#define INC    16
#define OUTC   32
#define HW_IN  128
#define HW_OUT 64
#define KTOT   144          // 3*3*16
#define NTOT   320
#define NPX    32768        // total output pixels (8 * 64 * 64)

// Tiles: CTA walks contiguous (pixel-tile, slab) units; 192 thr, 6 warps of 32x32
#define THREADS 192
#define CH_CTA  64
#define PX_CTA  96
#define AKB     304         // K row stride in bytes (152 fp16 = 19*16B, conflict-free)
#define PXTILES 342         // ceil(32768 / 96)
#define NSLABS  5
#define UNITS   (PXTILES * NSLABS)   // 1710
#define GRID    444                  // 148 SMs x 3 CTAs -> exactly 1 wave
#define UBASE   (UNITS / GRID)       // 3
#define UEXTRA  (UNITS - GRID * UBASE) // 378

#define X_BYTES (PX_CTA * AKB)          // 29184
#define W_BYTES (CH_CTA * AKB)          // 19456
#define OFF_X   0
#define OFF_W   (X_BYTES)
#define SMEM_BYTES (X_BYTES + W_BYTES)   // 48640 -> 3 CTAs/SM

// Pre-converted fp16 weights, [n][k] layout (n = mc*32+oc), k padded to 152
#define WKP 152
__device__ __half d_Wf[NTOT * WKP];

__device__ __forceinline__ uint32_t smem_u32(const void* p) {
    uint32_t a;
    asm("{ .reg .u64 t; cvta.to.shared.u64 t, %1; cvt.u32.u64 %0, t; }" : "=r"(a) : "l"(p));
    return a;
}
__device__ __forceinline__ void ldmx4(uint32_t addr, uint32_t &r0, uint32_t &r1,
                                      uint32_t &r2, uint32_t &r3) {
    asm volatile("ldmatrix.sync.aligned.m8n8.x4.shared.b16 {%0,%1,%2,%3}, [%4];"
                 : "=r"(r0), "=r"(r1), "=r"(r2), "=r"(r3) : "r"(addr));
}
__device__ __forceinline__ void mma16816(float* d, const uint32_t* a, const uint32_t* bb) {
    asm volatile(
        "mma.sync.aligned.m16n8k16.row.col.f32.f16.f16.f32 "
        "{%0,%1,%2,%3}, {%4,%5,%6,%7}, {%8,%9}, {%0,%1,%2,%3};"
        : "+f"(d[0]), "+f"(d[1]), "+f"(d[2]), "+f"(d[3])
        : "r"(a[0]), "r"(a[1]), "r"(a[2]), "r"(a[3]), "r"(bb[0]), "r"(bb[1]));
}
__device__ __forceinline__ void cp16(uint32_t saddr, const void* gptr) {
    asm volatile("cp.async.cg.shared.global [%0], [%1], 16;"
                 :: "r"(saddr), "l"(gptr) : "memory");
}
__device__ __forceinline__ void cp_commit() {
    asm volatile("cp.async.commit_group;" ::: "memory");
}
__device__ __forceinline__ void cp_wait0() {
    asm volatile("cp.async.wait_group 0;" ::: "memory");
}
__device__ __forceinline__ void fast_sincos(float v, float &s, float &c) {
    float t = rintf(v * 0.15915494309189535f);
    float r = fmaf(t, -6.2831855f, v);
    r = fmaf(t, 1.7484555e-7f, r);
    s = __sinf(r);
    c = __cosf(r);
}
__device__ __forceinline__ uint16_t hbits(__half h) {
    uint16_t u; *(__half*)&u = h; return u;
}

// ---------- weight materialization: DESTINATION-indexed (race-free) ----------
__global__ void prep_w_kernel(const float* __restrict__ mean,
                              const float* __restrict__ ls,
                              const float* __restrict__ eps) {
    int i = blockIdx.x * 256 + threadIdx.x;     // destination slot in [NTOT*WKP)
    if (i >= NTOT * WKP) return;
    int n  = i / WKP;          // n = mc*32 + oc
    int kk = i - n * WKP;      // 0..151
    float w = 0.f;
    if (kk < KTOT) {
        int mc = n >> 5;
        int oc = n & 31;
        float e = eps[(mc * KTOT + kk) * OUTC + oc];
        w = fmaf(e, expf(0.5f * ls[kk * OUTC + oc]), mean[kk * OUTC + oc]);
    }
    d_Wf[i] = __float2half_rn(w);
}

__global__ void __launch_bounds__(THREADS, 3)
conv_rff_hmma_kernel(const float* __restrict__ x,
                     const float* __restrict__ theta,
                     float* __restrict__ out) {
    extern __shared__ char sm[];
    const uint32_t smb = smem_u32(sm);

    const int tid  = threadIdx.x;
    const int wid  = tid >> 5;
    const int lane = tid & 31;

    // Contiguous unit range for this CTA; odd CTAs walk it in reverse
    const int g   = blockIdx.x;
    const int cnt = UBASE + (g < UEXTRA ? 1 : 0);
    const int u0  = g * UBASE + (g < UEXTRA ? g : UEXTRA);
    const bool rev = (g & 1);

    // Warp tiling constants
    const int chbase = (wid & 1) * 32;    // 0 or 32
    const int pxw    = (wid >> 1) * 32;   // 0, 32, 64
    const uint32_t a_off = (uint32_t)((lane & 15) * AKB + (lane >> 4) * 16);
    const uint32_t b_off = (uint32_t)(((lane >> 4) * 8 + (lane & 7)) * AKB +
                                      ((lane >> 3) & 1) * 16);
    const uint32_t wbase = smb + OFF_W + chbase * AKB + a_off;
    const uint32_t xbase = smb + OFF_X + pxw * AKB + b_off;
    const float scale = expf(0.5f * theta[0]) * 0.0027621358640644f; // 1/sqrt(32*64*64)
    const int l2 = lane >> 2;
    const int l3 = lane & 3;

    auto unit_at = [&](int ui) { return rev ? (u0 + cnt - 1 - ui) : (u0 + ui); };

    auto stage_X = [&](int tile) {
        const int px0 = tile * PX_CTA;
        char* Xs = sm + OFF_X;
        #pragma unroll 3
        for (int i = tid; i < PX_CTA * (KTOT / 4); i += THREADS) {   // 18 iters
            int q  = i / PX_CTA;        // k-quad 0..35
            int px = i - q * PX_CTA;
            int k0 = q * 4;
            int kh  = k0 / 48;
            int rem = k0 - kh * 48;
            int kw  = rem >> 4;
            int c0  = rem & 15;         // quads never straddle (kh,kw)
            int gp  = px0 + px;
            int b   = gp >> 12;
            int oy  = (gp >> 6) & 63;
            int ox  = gp & 63;
            int iy  = 2 * oy + kh - 1;
            int ix  = 2 * ox + kw - 1;
            bool valid = (gp < NPX) && ((unsigned)iy < (unsigned)HW_IN)
                                     && ((unsigned)ix < (unsigned)HW_IN);
            const float* xp = x + (((size_t)b * INC + c0) * HW_IN + iy) * HW_IN + ix;
            float v[4];
            #pragma unroll
            for (int j = 0; j < 4; ++j)
                v[j] = valid ? xp[(size_t)j * HW_IN * HW_IN] : 0.f;
            uint16_t hu[4];
            #pragma unroll
            for (int j = 0; j < 4; ++j)
                hu[j] = hbits(__float2half_rn(v[j]));
            uint32_t off = (uint32_t)(px * AKB + k0 * 2);
            *(uint2*)(Xs + off) = make_uint2((uint32_t)hu[0] | ((uint32_t)hu[1] << 16),
                                             (uint32_t)hu[2] | ((uint32_t)hu[3] << 16));
        }
    };

    auto prefetch_W = [&](int slab) {
        const char* gw = (const char*)(d_Wf + (size_t)slab * CH_CTA * WKP);
        #pragma unroll 2
        for (int i = tid; i < W_BYTES / 16; i += THREADS) {   // 1216 chunks
            cp16(smb + OFF_W + i * 16, gw + i * 16);
        }
        cp_commit();
    };

    // ---- prologue: stage first X + prefetch first W ----
    {
        int u = unit_at(0);
        prefetch_W(u % NSLABS);
        stage_X(u / NSLABS);
    }

    int cur_tile = unit_at(0) / NSLABS;

    for (int ui = 0; ui < cnt; ++ui) {
        const int u    = unit_at(ui);
        const int tile = u / NSLABS;
        const int slab = u - tile * NSLABS;
        const int px0  = tile * PX_CTA;

        cp_wait0();
        __syncthreads();   // X + W visible to all warps

        float acc[2][4][4];
        #pragma unroll
        for (int mi = 0; mi < 2; ++mi)
            #pragma unroll
            for (int ni = 0; ni < 4; ++ni)
                #pragma unroll
                for (int c = 0; c < 4; ++c)
                    acc[mi][ni][c] = 0.f;

        // ---- fp16 mainloop: per kc 4 ldsm.x4 + 8 MMA ----
        #pragma unroll
        for (int kc = 0; kc < 9; ++kc) {
            const uint32_t kb = (uint32_t)kc * 32;
            uint32_t bf[4][2];
            {
                uint32_t r0, r1, r2, r3;
                ldmx4(xbase + kb, r0, r1, r2, r3);
                bf[0][0] = r0; bf[0][1] = r1; bf[1][0] = r2; bf[1][1] = r3;
                ldmx4(xbase + 16 * AKB + kb, r0, r1, r2, r3);
                bf[2][0] = r0; bf[2][1] = r1; bf[3][0] = r2; bf[3][1] = r3;
            }
            uint32_t a0[4], a1[4];
            ldmx4(wbase + kb, a0[0], a0[1], a0[2], a0[3]);
            ldmx4(wbase + 16 * AKB + kb, a1[0], a1[1], a1[2], a1[3]);
            #pragma unroll
            for (int ni = 0; ni < 4; ++ni) {
                mma16816(acc[0][ni], a0, bf[ni]);
                mma16816(acc[1][ni], a1, bf[ni]);
            }
        }

        __syncthreads();   // all warps done reading X/W; buffers may be refilled

        // ---- prefetch next unit's W under the epilogue ----
        int next_tile = -1;
        if (ui + 1 < cnt) {
            int un = unit_at(ui + 1);
            prefetch_W(un % NSLABS);
            next_tile = un / NSLABS;
        }

        // ---- Epilogue for this unit (overlaps W prefetch latency) ----
        #pragma unroll
        for (int mi = 0; mi < 2; ++mi) {
            #pragma unroll
            for (int msub = 0; msub < 2; ++msub) {
                int ch  = chbase + mi * 16 + msub * 8 + l2;
                int ngl = slab * CH_CTA + ch;                // global channel [0,320)
                int chan = (ngl >> 5) * 64 + (ngl & 31);     // mc*64 + oc
                #pragma unroll
                for (int ni = 0; ni < 4; ++ni) {
                    int gp = px0 + pxw + ni * 8 + 2 * l3;
                    if (gp >= NPX) continue;
                    int b  = gp >> 12;
                    int oy = (gp >> 6) & 63;
                    int ox = gp & 63;
                    float* basec = out + ((size_t)(b * (MCC * 2 * OUTC) + chan)) * (HW_OUT * HW_OUT)
                                       + oy * HW_OUT + ox;
                    float* bases = basec + (size_t)OUTC * HW_OUT * HW_OUT;
                    float v0 = acc[mi][ni][msub * 2 + 0];
                    float v1 = acc[mi][ni][msub * 2 + 1];
                    float s0, c0, s1, c1;
                    fast_sincos(v0, s0, c0);
                    fast_sincos(v1, s1, c1);
                    *(float2*)basec = make_float2(scale * c0, scale * c1);
                    *(float2*)bases = make_float2(scale * s0, scale * s1);
                }
            }
        }

        // ---- restage X if the next unit is a new pixel tile ----
        if (next_tile >= 0 && next_tile != cur_tile) {
            stage_X(next_tile);
            cur_tile = next_tile;
        }
    }
}

extern "C" void kernel_launch(void* const* d_in, const int* in_sizes, int n_in,
                              void* d_out, int out_size) {
    const float* x     = (const float*)d_in[0];
    const float* theta = (const float*)d_in[1];
    const float* mean  = (const float*)d_in[2];
    const float* ls    = (const float*)d_in[3];
    const float* eps   = (const float*)d_in[4];
    float* out = (float*)d_out;

    prep_w_kernel<<<(NTOT * WKP + 255) / 256, 256>>>(mean, ls, eps);

    cudaFuncSetAttribute(conv_rff_hmma_kernel,
                         cudaFuncAttributeMaxDynamicSharedMemorySize, SMEM_BYTES);
    conv_rff_hmma_kernel<<<GRID, THREADS, SMEM_BYTES>>>(x, theta, out);
}